// round 12
// baseline (speedup 1.0000x reference)
#include <cuda_runtime.h>
#include <cstdint>

// Problem constants
#define DD   4096
#define OBJN 20
#define MCNT 1000
#define FR   20
#define BB   4
#define QQ   4
#define NROWS 32      // compacted rows: 16 high + 16 low
#define MPB  4        // memory rows per fused block
#define NFUSED 500    // (MCNT/MPB)*2
#define NPLAIN 6400   // 320 frame-slots * 20 obj
// grid: [0,2000): 1:3 fused/copy interleave; [2000,6900): pure copy
#define REGA 2000
#define GRIDN 6900

#define RP_ELEMS 26214400ull          // Q*B*F*OBJ*D
#define OUT_HIGH (2ull*RP_ELEMS)      // 52428800
#define OUT_LOW  (2ull*RP_ELEMS + 16ull)

typedef unsigned long long ull;

// ---------------- scratch (device globals; no allocation allowed) ----------
__device__ int   g_high[16];
__device__ int   g_low[16];
__device__ int   g_rowbf[32];                 // compact row -> b*20+f
__device__ float g_invn[BB*FR*OBJN];          // per-region inverse norms
__device__ float g_Rmax[BB*FR*DD];            // normalized max-pooled input rows
__device__ float g_score[2*NROWS*1024];       // [sel][row][m] final scores
__device__ int   g_sim[64];                   // [sel][32] argmax results
__device__ int   g_ctr;                       // fused-done counter

// ---------------- helpers ---------------------------------------------------
__device__ __forceinline__ float blockReduceSum256(float v, float* sh) {
    #pragma unroll
    for (int o = 16; o > 0; o >>= 1) v += __shfl_xor_sync(0xffffffffu, v, o);
    int lane = threadIdx.x & 31, w = threadIdx.x >> 5;
    if (lane == 0) sh[w] = v;
    __syncthreads();
    if (threadIdx.x < 32) {
        float r = (threadIdx.x < 8) ? sh[threadIdx.x] : 0.f;
        #pragma unroll
        for (int o = 4; o > 0; o >>= 1) r += __shfl_xor_sync(0xffffffffu, r, o);
        if (threadIdx.x == 0) sh[0] = r;
    }
    __syncthreads();
    float res = sh[0];
    __syncthreads();
    return res;
}

__device__ __forceinline__ void ffma2(ull& d, ull a, ull b) {
    asm("fma.rn.f32x2 %0, %1, %2, %0;" : "+l"(d) : "l"(a), "l"(b));
}
__device__ __forceinline__ ull packf2(float x, float y) {
    ull r; asm("mov.b64 %0, {%1,%2};" : "=l"(r) : "f"(x), "f"(y)); return r;
}
__device__ __forceinline__ float unpack_add(ull a) {
    unsigned lo, hi;
    asm("mov.b64 {%0,%1}, %2;" : "=r"(lo), "=r"(hi) : "l"(a));
    return __uint_as_float(lo) + __uint_as_float(hi);
}

// ---------------- K1: idx (block 0) + per-region norms + normalized maxpool -
__global__ void __launch_bounds__(256) k_rmax(const float* __restrict__ qr,
                                              const int* __restrict__ rnd,
                                              const float* __restrict__ inp) {
    int bf = blockIdx.x;             // b*20+f, 80 blocks
    int t  = threadIdx.x;

    if (bf == 0 && t == 0) g_ctr = 0;        // reset for graph replays
    if (bf == 0 && t < 16) {
        int b = t >> 2;
        const float* v = qr + t * FR;   // [B,Q,F], t=b*Q+q
        int hi = 0; float hv = v[0];
        for (int i = 1; i < FR; i++) { float x = v[i]; if (x > hv) { hv = x; hi = i; } }
        int r = rnd[t];
        int lo = 0;
        for (int i = 0; i < FR; i++) {
            int rank = 0;
            float c = v[i];
            for (int j = 0; j < FR; j++) {
                float a = v[j];
                rank += (a < c) || (a == c && j < i);
            }
            if (rank == r) { lo = i; break; }
        }
        g_high[t] = hi;
        g_low[t]  = lo;
        g_rowbf[t]      = b * FR + hi;
        g_rowbf[16 + t] = b * FR + lo;
    }

    __shared__ float sh[32];
    __shared__ float s_inv[OBJN];
    const float* base = inp + (size_t)bf * (OBJN * DD);

    for (int o = 0; o < OBJN; o++) {
        const float4* p = (const float4*)(base + o * DD);
        float s = 0.f;
        #pragma unroll
        for (int i = 0; i < 4; i++) {
            float4 v = __ldg(p + t + i * 256);
            s += v.x*v.x + v.y*v.y + v.z*v.z + v.w*v.w;
        }
        float tot = blockReduceSum256(s, sh);
        if (t == 0) s_inv[o] = 1.0f / fmaxf(sqrtf(tot), 1e-12f);
    }
    __syncthreads();
    if (t < OBJN) g_invn[bf * OBJN + t] = s_inv[t];

    float4 mx[4];
    #pragma unroll
    for (int i = 0; i < 4; i++) mx[i] = make_float4(-3.4e38f, -3.4e38f, -3.4e38f, -3.4e38f);
    for (int o = 0; o < OBJN; o++) {
        float inv = s_inv[o];
        const float4* p = (const float4*)(base + o * DD);
        #pragma unroll
        for (int i = 0; i < 4; i++) {
            float4 v = __ldg(p + t + i * 256);
            mx[i].x = fmaxf(mx[i].x, v.x * inv);
            mx[i].y = fmaxf(mx[i].y, v.y * inv);
            mx[i].z = fmaxf(mx[i].z, v.z * inv);
            mx[i].w = fmaxf(mx[i].w, v.w * inv);
        }
    }
    float s = 0.f;
    #pragma unroll
    for (int i = 0; i < 4; i++) s += mx[i].x*mx[i].x + mx[i].y*mx[i].y + mx[i].z*mx[i].z + mx[i].w*mx[i].w;
    float tot = blockReduceSum256(s, sh);
    float inv2 = 1.0f / fmaxf(sqrtf(tot), 1e-12f);
    float4* op = (float4*)(g_Rmax + (size_t)bf * DD);
    #pragma unroll
    for (int i = 0; i < 4; i++) {
        float4 v = mx[i];
        v.x *= inv2; v.y *= inv2; v.z *= inv2; v.w *= inv2;
        op[t + i * 256] = v;
    }
}

// ---------------- K2: MIXED kernel: fused mem pipeline + plain output copy --
// Blocks [0,2000): every 4th is fused (500 total), others copy (1500).
// Blocks [2000,6900): pure copy (4900). Dense early fused population keeps
// the 655MB read stream saturated from wave 1 while copies fill write BW.
// The LAST fused block to finish also performs the argmax inline.
__global__ void __launch_bounds__(256) k_main(const float* __restrict__ mem1,
                                              const float* __restrict__ mem2,
                                              const float* __restrict__ inp,
                                              float* __restrict__ out) {
    int bx = blockIdx.x;
    int t  = threadIdx.x;

    __shared__ float sh[32];
    __shared__ float s_inv[MPB];
    __shared__ int   rb[NROWS];
    __shared__ float s_red[NROWS][8][MPB];
    __shared__ int   s_last;

    bool fused = (bx < REGA) && ((bx & 3) == 0);
    if (fused) {
        // ----- fused memory-bank work -----
        int f_id = bx >> 2;                  // 0..499
        int sel  = f_id & 1;
        int m0   = (f_id >> 1) * MPB;
        const float* mem = sel ? mem2 : mem1;
        int lane = t & 31, w = t >> 5;
        int rstart = sel ? 0 : 16;           // sel0 only needs low rows
        if (t < NROWS) rb[t] = g_rowbf[t] * (DD / 4);

        float4 pm[MPB][4];
        #pragma unroll
        for (int mi = 0; mi < MPB; mi++) {
            #pragma unroll
            for (int i = 0; i < 4; i++)
                pm[mi][i] = make_float4(-3.4e38f, -3.4e38f, -3.4e38f, -3.4e38f);
            const float4* base = (const float4*)(mem + (size_t)(m0 + mi) * (OBJN * DD));
            for (int o = 0; o < OBJN; o++) {
                const float4* p = base + o * (DD / 4);
                #pragma unroll
                for (int i = 0; i < 4; i++) {
                    float4 v = __ldcs(p + t + i * 256);
                    pm[mi][i].x = fmaxf(pm[mi][i].x, v.x);
                    pm[mi][i].y = fmaxf(pm[mi][i].y, v.y);
                    pm[mi][i].z = fmaxf(pm[mi][i].z, v.z);
                    pm[mi][i].w = fmaxf(pm[mi][i].w, v.w);
                }
            }
            float s = 0.f;
            #pragma unroll
            for (int i = 0; i < 4; i++)
                s += pm[mi][i].x*pm[mi][i].x + pm[mi][i].y*pm[mi][i].y
                   + pm[mi][i].z*pm[mi][i].z + pm[mi][i].w*pm[mi][i].w;
            float tot = blockReduceSum256(s, sh);    // syncthreads covers rb
            if (t == 0) s_inv[mi] = 1.0f / fmaxf(sqrtf(tot), 1e-12f);
        }

        ull pp[MPB][8];
        #pragma unroll
        for (int mi = 0; mi < MPB; mi++)
            #pragma unroll
            for (int i = 0; i < 4; i++) {
                pp[mi][2*i]   = packf2(pm[mi][i].x, pm[mi][i].y);
                pp[mi][2*i+1] = packf2(pm[mi][i].z, pm[mi][i].w);
            }

        for (int r = rstart; r < NROWS; r++) {
            const float4* R4 = ((const float4*)g_Rmax) + rb[r] + t;
            ull a0 = 0ull, a1 = 0ull, a2 = 0ull, a3 = 0ull;
            #pragma unroll
            for (int i = 0; i < 4; i++) {
                float4 rv = __ldg(R4 + i * 256);
                ull r0 = packf2(rv.x, rv.y), r1 = packf2(rv.z, rv.w);
                ffma2(a0, pp[0][2*i], r0); ffma2(a0, pp[0][2*i+1], r1);
                ffma2(a1, pp[1][2*i], r0); ffma2(a1, pp[1][2*i+1], r1);
                ffma2(a2, pp[2][2*i], r0); ffma2(a2, pp[2][2*i+1], r1);
                ffma2(a3, pp[3][2*i], r0); ffma2(a3, pp[3][2*i+1], r1);
            }
            float p0 = unpack_add(a0), p1 = unpack_add(a1);
            float p2 = unpack_add(a2), p3 = unpack_add(a3);
            #pragma unroll
            for (int o = 16; o > 0; o >>= 1) {
                p0 += __shfl_xor_sync(0xffffffffu, p0, o);
                p1 += __shfl_xor_sync(0xffffffffu, p1, o);
                p2 += __shfl_xor_sync(0xffffffffu, p2, o);
                p3 += __shfl_xor_sync(0xffffffffu, p3, o);
            }
            if (lane == 0) {
                s_red[r][w][0] = p0; s_red[r][w][1] = p1;
                s_red[r][w][2] = p2; s_red[r][w][3] = p3;
            }
        }
        __syncthreads();
        if (t < (NROWS * MPB)) {
            int r = t >> 2, mi = t & 3;
            if (r >= rstart) {
                float s = 0.f;
                #pragma unroll
                for (int ww = 0; ww < 8; ww++) s += s_red[r][ww][mi];
                g_score[((size_t)sel * NROWS + r) * 1024 + m0 + mi] = s * s_inv[mi];
            }
        }

        // ----- last-done fused block performs the argmax inline -----
        __syncthreads();
        if (t == 0) {
            __threadfence();
            s_last = (atomicAdd(&g_ctr, 1) == NFUSED - 1) ? 1 : 0;
        }
        __syncthreads();
        if (s_last) {
            __threadfence();
            int lane2 = t & 31, w2 = t >> 5;
            // rows 16..63 of g_score (48 rows); warp w2 handles rows 16+w2, +8
            for (int row = 16 + w2; row < 64; row += 8) {
                const float* sc = g_score + (size_t)row * 1024;
                ull best = 0ull;
                for (int m = lane2; m < MCNT; m += 32) {
                    unsigned u = __float_as_uint(sc[m]);
                    u ^= (u >> 31) ? 0xFFFFFFFFu : 0x80000000u;
                    ull pv = ((ull)u << 32) | (unsigned)(0xFFFFFFFFu - (unsigned)m);
                    best = (pv > best) ? pv : best;
                }
                #pragma unroll
                for (int o = 16; o > 0; o >>= 1) {
                    ull x = __shfl_xor_sync(0xffffffffu, best, o);
                    best = (x > best) ? x : best;
                }
                if (lane2 == 0) {
                    int sim = (int)(0xFFFFFFFFu - (unsigned)(best & 0xFFFFFFFFu));
                    g_sim[row] = sim;
                    int sel2 = row >> 5, r2 = row & 31;
                    if (sel2 == 1 && r2 < 16) {
                        int b = r2 >> 2, q = r2 & 3;
                        out[OUT_HIGH + q * 4 + b] = (float)sim;  // sim2 @ high
                    }
                    if (sel2 == 0 && r2 >= 16) {
                        int bq = r2 - 16;
                        int b = bq >> 2, q = bq & 3;
                        out[OUT_LOW + q * 4 + b] = (float)sim;   // sim1 @ low
                    }
                }
            }
            if (t == 0) __threadfence();     // publish sims before kernel end
        }
    } else {
        // ----- plain output copy tile -----
        int p_id = (bx < REGA) ? (bx - (bx >> 2) - 1) : (1500 + (bx - REGA));
        int id = p_id / OBJN;            // 0..319 == q*80 + b*20 + f
        int o  = p_id - id * OBJN;
        int q  = id / 80;
        int rem = id - q * 80;
        int b  = rem / FR;
        int f  = rem - b * FR;
        int bq = b * QQ + q;
        if (f == g_high[bq] || f == g_low[bq]) return;   // k_out_spec handles

        size_t outoff = ((size_t)id * OBJN + o) * DD;
        float4* op = (float4*)(out + outoff);                 // Rp
        float4* on = (float4*)(out + RP_ELEMS + outoff);      // Rn
        const float4* pr = (const float4*)(inp + (((size_t)(b * FR + f)) * OBJN + o) * DD);
        float invn = g_invn[(b * FR + f) * OBJN + o];

        #pragma unroll
        for (int i = 0; i < 4; i++) {
            float4 v = __ldg(pr + t + i * 256);
            v.x *= invn; v.y *= invn; v.z *= invn; v.w *= invn;
            __stcs(op + t + i * 256, v);
            __stcs(on + t + i * 256, v);
        }
    }
}

// ---------------- K3: hi/lo output frames (needs g_sim) ---------------------
__global__ void __launch_bounds__(256) k_out_spec(const float* __restrict__ inp,
                                                  const float* __restrict__ mem1,
                                                  const float* __restrict__ mem2,
                                                  float* __restrict__ out) {
    int s  = blockIdx.x;             // 0..31: [kind][bq]
    int o  = blockIdx.y;             // 0..19
    int bq = s & 15;
    int kind = s >> 4;               // 0: f=hi, 1: f=lo
    int b = bq >> 2, q = bq & 3;
    int hi = g_high[bq], lo = g_low[bq];
    int f  = kind ? lo : hi;
    int id = q * 80 + b * FR + f;
    int t  = threadIdx.x;

    size_t outoff = ((size_t)id * OBJN + o) * DD;
    float4* op = (float4*)(out + outoff);                 // Rp
    float4* on = (float4*)(out + RP_ELEMS + outoff);      // Rn
    const float4* pr = (const float4*)(inp + (((size_t)(b * FR + f)) * OBJN + o) * DD);
    float invn = g_invn[(b * FR + f) * OBJN + o];

    if (kind == 0) {
        // f == hi: Rn <- mem2[sim2 @ low]; Rp <- R
        int sm = g_sim[32 + 16 + bq];
        const float4* pm = (const float4*)(mem2 + (size_t)sm * (OBJN * DD) + o * DD);
        #pragma unroll
        for (int i = 0; i < 4; i++) {
            float4 v = __ldg(pr + t + i * 256);
            v.x *= invn; v.y *= invn; v.z *= invn; v.w *= invn;
            __stcs(op + t + i * 256, v);
            float4 w = __ldg(pm + t + i * 256);
            __stcs(on + t + i * 256, w);
        }
    } else {
        // f == lo: Rp <- mem1[sim1 @ low]; Rn <- R
        int sm = g_sim[16 + bq];
        const float4* pm = (const float4*)(mem1 + (size_t)sm * (OBJN * DD) + o * DD);
        #pragma unroll
        for (int i = 0; i < 4; i++) {
            float4 w = __ldg(pm + t + i * 256);
            __stcs(op + t + i * 256, w);
            float4 v = __ldg(pr + t + i * 256);
            v.x *= invn; v.y *= invn; v.z *= invn; v.w *= invn;
            __stcs(on + t + i * 256, v);
        }
    }
}

// ---------------- launch -----------------------------------------------------
extern "C" void kernel_launch(void* const* d_in, const int* in_sizes, int n_in,
                              void* d_out, int out_size) {
    const float* qr   = (const float*)d_in[0];   // [4,4,20]
    const float* inp  = (const float*)d_in[1];   // [4,20,20,4096]
    const float* mem1 = (const float*)d_in[2];   // [1000,81920]
    const float* mem2 = (const float*)d_in[3];   // [1000,81920]
    const int*   rnd  = (const int*)d_in[4];     // [4,4,1]
    float* out = (float*)d_out;

    k_rmax<<<80, 256>>>(qr, rnd, inp);
    k_main<<<GRIDN, 256>>>(mem1, mem2, inp, out);
    k_out_spec<<<dim3(32, OBJN), 256>>>(inp, mem1, mem2, out);
}

// round 14
// speedup vs baseline: 1.0487x; 1.0487x over previous
#include <cuda_runtime.h>
#include <cstdint>

// Problem constants
#define DD   4096
#define OBJN 20
#define MCNT 1000
#define FR   20
#define BB   4
#define QQ   4
#define NROWS 32      // compacted rows: 16 high + 16 low
#define MPB  4        // memory rows per fused block
#define NFUSED 500    // (MCNT/MPB)*2
#define NPLAIN 6400   // 320 frame-slots * 20 obj
#define ILV  14       // uniform interleave: every ILV-th block is fused
#define GRIDN 7000

#define RP_ELEMS 26214400ull          // Q*B*F*OBJ*D
#define OUT_HIGH (2ull*RP_ELEMS)      // 52428800
#define OUT_LOW  (2ull*RP_ELEMS + 16ull)

typedef unsigned long long ull;

// ---------------- scratch (device globals; no allocation allowed) ----------
__device__ int   g_high[16];
__device__ int   g_low[16];
__device__ int   g_rowbf[32];                 // compact row -> b*20+f
__device__ float g_invn[BB*FR*OBJN];          // per-region inverse norms
__device__ float g_Rmax[BB*FR*DD];            // UNNORMALIZED max-pooled rows
                                              // (per-row scale can't change argmax)
__device__ float g_score[2*NROWS*1024];       // [sel][row][m] scores (row-scaled)
__device__ int   g_sim[64];                   // [sel][32] argmax results
__device__ int   g_ctr;                       // fused-done counter

// ---------------- helpers ---------------------------------------------------
__device__ __forceinline__ float blockReduceSum256(float v, float* sh) {
    #pragma unroll
    for (int o = 16; o > 0; o >>= 1) v += __shfl_xor_sync(0xffffffffu, v, o);
    int lane = threadIdx.x & 31, w = threadIdx.x >> 5;
    if (lane == 0) sh[w] = v;
    __syncthreads();
    if (threadIdx.x < 32) {
        float r = (threadIdx.x < 8) ? sh[threadIdx.x] : 0.f;
        #pragma unroll
        for (int o = 4; o > 0; o >>= 1) r += __shfl_xor_sync(0xffffffffu, r, o);
        if (threadIdx.x == 0) sh[0] = r;
    }
    __syncthreads();
    float res = sh[0];
    __syncthreads();
    return res;
}

__device__ __forceinline__ void ffma2(ull& d, ull a, ull b) {
    asm("fma.rn.f32x2 %0, %1, %2, %0;" : "+l"(d) : "l"(a), "l"(b));
}
__device__ __forceinline__ ull packf2(float x, float y) {
    ull r; asm("mov.b64 %0, {%1,%2};" : "=l"(r) : "f"(x), "f"(y)); return r;
}
__device__ __forceinline__ float unpack_add(ull a) {
    unsigned lo, hi;
    asm("mov.b64 {%0,%1}, %2;" : "=r"(lo), "=r"(hi) : "l"(a));
    return __uint_as_float(lo) + __uint_as_float(hi);
}

// ---------------- K1: per-region inverse norms (full-chip) + idx side-work --
__global__ void __launch_bounds__(256) k_norms(const float* __restrict__ qr,
                                               const int* __restrict__ rnd,
                                               const float* __restrict__ inp) {
    int row = blockIdx.x;            // 0..1599 == bf*20 + o
    int t   = threadIdx.x;

    if (row == 0 && t == 0) g_ctr = 0;       // reset for graph replays
    if (row == 0 && t >= 32 && t < 48) {     // warp 1: top-k / rank select
        int tt = t - 32;
        int b = tt >> 2;
        const float* v = qr + tt * FR;
        int hi = 0; float hv = v[0];
        for (int i = 1; i < FR; i++) { float x = v[i]; if (x > hv) { hv = x; hi = i; } }
        int r = rnd[tt];
        int lo = 0;
        for (int i = 0; i < FR; i++) {
            int rank = 0;
            float c = v[i];
            for (int j = 0; j < FR; j++) {
                float a = v[j];
                rank += (a < c) || (a == c && j < i);
            }
            if (rank == r) { lo = i; break; }
        }
        g_high[tt] = hi;
        g_low[tt]  = lo;
        g_rowbf[tt]      = b * FR + hi;
        g_rowbf[16 + tt] = b * FR + lo;
    }

    __shared__ float sh[32];
    const float4* p = (const float4*)(inp + (size_t)row * DD);
    float s = 0.f;
    #pragma unroll
    for (int i = 0; i < 4; i++) {
        float4 v = __ldg(p + t + i * 256);
        s += v.x*v.x + v.y*v.y + v.z*v.z + v.w*v.w;
    }
    float tot = blockReduceSum256(s, sh);
    if (t == 0) g_invn[row] = 1.0f / fmaxf(sqrtf(tot), 1e-12f);
}

// ---------------- K2: scaled max-pool (column-sliced, input L2-hot) ---------
__global__ void __launch_bounds__(256) k_pool(const float* __restrict__ inp) {
    int bf = blockIdx.x;             // 0..79
    int c  = blockIdx.y * 256 + threadIdx.x;   // f4 col 0..1023
    __shared__ float s_inv[OBJN];
    if (threadIdx.x < OBJN) s_inv[threadIdx.x] = g_invn[bf * OBJN + threadIdx.x];
    __syncthreads();

    const float4* base = (const float4*)(inp + (size_t)bf * (OBJN * DD));
    float4 mx = make_float4(-3.4e38f, -3.4e38f, -3.4e38f, -3.4e38f);
    #pragma unroll 4
    for (int o = 0; o < OBJN; o++) {
        float inv = s_inv[o];
        float4 v = __ldg(base + o * (DD / 4) + c);
        mx.x = fmaxf(mx.x, v.x * inv);
        mx.y = fmaxf(mx.y, v.y * inv);
        mx.z = fmaxf(mx.z, v.z * inv);
        mx.w = fmaxf(mx.w, v.w * inv);
    }
    ((float4*)(g_Rmax + (size_t)bf * DD))[c] = mx;   // unnormalized pooled row
}

// ---------------- K3: MIXED kernel: fused mem pipeline + plain output copy --
// Uniform 1:14 interleave (round-11 proven). Last fused block does argmax.
__global__ void __launch_bounds__(256) k_main(const float* __restrict__ mem1,
                                              const float* __restrict__ mem2,
                                              const float* __restrict__ inp,
                                              float* __restrict__ out) {
    int bx = blockIdx.x;
    int t  = threadIdx.x;

    __shared__ float sh[32];
    __shared__ float s_inv[MPB];
    __shared__ int   rb[NROWS];
    __shared__ float s_red[NROWS][8][MPB];
    __shared__ int   s_last;

    if (bx % ILV == 0) {
        // ----- fused memory-bank work -----
        int f_id = bx / ILV;                 // 0..499
        int sel  = f_id & 1;
        int m0   = (f_id >> 1) * MPB;
        const float* mem = sel ? mem2 : mem1;
        int lane = t & 31, w = t >> 5;
        int rstart = sel ? 0 : 16;           // sel0 only needs low rows
        if (t < NROWS) rb[t] = g_rowbf[t] * (DD / 4);

        float4 pm[MPB][4];
        #pragma unroll
        for (int mi = 0; mi < MPB; mi++) {
            #pragma unroll
            for (int i = 0; i < 4; i++)
                pm[mi][i] = make_float4(-3.4e38f, -3.4e38f, -3.4e38f, -3.4e38f);
            const float4* base = (const float4*)(mem + (size_t)(m0 + mi) * (OBJN * DD));
            for (int o = 0; o < OBJN; o++) {
                const float4* p = base + o * (DD / 4);
                #pragma unroll
                for (int i = 0; i < 4; i++) {
                    float4 v = __ldcs(p + t + i * 256);
                    pm[mi][i].x = fmaxf(pm[mi][i].x, v.x);
                    pm[mi][i].y = fmaxf(pm[mi][i].y, v.y);
                    pm[mi][i].z = fmaxf(pm[mi][i].z, v.z);
                    pm[mi][i].w = fmaxf(pm[mi][i].w, v.w);
                }
            }
            float s = 0.f;
            #pragma unroll
            for (int i = 0; i < 4; i++)
                s += pm[mi][i].x*pm[mi][i].x + pm[mi][i].y*pm[mi][i].y
                   + pm[mi][i].z*pm[mi][i].z + pm[mi][i].w*pm[mi][i].w;
            float tot = blockReduceSum256(s, sh);    // syncthreads covers rb
            if (t == 0) s_inv[mi] = 1.0f / fmaxf(sqrtf(tot), 1e-12f);
        }

        ull pp[MPB][8];
        #pragma unroll
        for (int mi = 0; mi < MPB; mi++)
            #pragma unroll
            for (int i = 0; i < 4; i++) {
                pp[mi][2*i]   = packf2(pm[mi][i].x, pm[mi][i].y);
                pp[mi][2*i+1] = packf2(pm[mi][i].z, pm[mi][i].w);
            }

        for (int r = rstart; r < NROWS; r++) {
            const float4* R4 = ((const float4*)g_Rmax) + rb[r] + t;
            ull a0 = 0ull, a1 = 0ull, a2 = 0ull, a3 = 0ull;
            #pragma unroll
            for (int i = 0; i < 4; i++) {
                float4 rv = __ldg(R4 + i * 256);
                ull r0 = packf2(rv.x, rv.y), r1 = packf2(rv.z, rv.w);
                ffma2(a0, pp[0][2*i], r0); ffma2(a0, pp[0][2*i+1], r1);
                ffma2(a1, pp[1][2*i], r0); ffma2(a1, pp[1][2*i+1], r1);
                ffma2(a2, pp[2][2*i], r0); ffma2(a2, pp[2][2*i+1], r1);
                ffma2(a3, pp[3][2*i], r0); ffma2(a3, pp[3][2*i+1], r1);
            }
            float p0 = unpack_add(a0), p1 = unpack_add(a1);
            float p2 = unpack_add(a2), p3 = unpack_add(a3);
            #pragma unroll
            for (int o = 16; o > 0; o >>= 1) {
                p0 += __shfl_xor_sync(0xffffffffu, p0, o);
                p1 += __shfl_xor_sync(0xffffffffu, p1, o);
                p2 += __shfl_xor_sync(0xffffffffu, p2, o);
                p3 += __shfl_xor_sync(0xffffffffu, p3, o);
            }
            if (lane == 0) {
                s_red[r][w][0] = p0; s_red[r][w][1] = p1;
                s_red[r][w][2] = p2; s_red[r][w][3] = p3;
            }
        }
        __syncthreads();
        if (t < (NROWS * MPB)) {
            int r = t >> 2, mi = t & 3;
            if (r >= rstart) {
                float s = 0.f;
                #pragma unroll
                for (int ww = 0; ww < 8; ww++) s += s_red[r][ww][mi];
                g_score[((size_t)sel * NROWS + r) * 1024 + m0 + mi] = s * s_inv[mi];
            }
        }

        // ----- last-done fused block performs the argmax inline -----
        __syncthreads();
        if (t == 0) {
            __threadfence();
            s_last = (atomicAdd(&g_ctr, 1) == NFUSED - 1) ? 1 : 0;
        }
        __syncthreads();
        if (s_last) {
            __threadfence();
            int lane2 = t & 31, w2 = t >> 5;
            for (int row = 16 + w2; row < 64; row += 8) {
                const float* sc = g_score + (size_t)row * 1024;
                ull best = 0ull;
                for (int m = lane2; m < MCNT; m += 32) {
                    unsigned u = __float_as_uint(sc[m]);
                    u ^= (u >> 31) ? 0xFFFFFFFFu : 0x80000000u;
                    ull pv = ((ull)u << 32) | (unsigned)(0xFFFFFFFFu - (unsigned)m);
                    best = (pv > best) ? pv : best;
                }
                #pragma unroll
                for (int o = 16; o > 0; o >>= 1) {
                    ull x = __shfl_xor_sync(0xffffffffu, best, o);
                    best = (x > best) ? x : best;
                }
                if (lane2 == 0) {
                    int sim = (int)(0xFFFFFFFFu - (unsigned)(best & 0xFFFFFFFFu));
                    g_sim[row] = sim;
                    int sel2 = row >> 5, r2 = row & 31;
                    if (sel2 == 1 && r2 < 16) {
                        int b = r2 >> 2, q = r2 & 3;
                        out[OUT_HIGH + q * 4 + b] = (float)sim;  // sim2 @ high
                    }
                    if (sel2 == 0 && r2 >= 16) {
                        int bq = r2 - 16;
                        int b = bq >> 2, q = bq & 3;
                        out[OUT_LOW + q * 4 + b] = (float)sim;   // sim1 @ low
                    }
                }
            }
            if (t == 0) __threadfence();
        }
    } else {
        // ----- plain output copy tile -----
        int p_id = bx - bx / ILV - 1;
        if (p_id >= NPLAIN) return;
        int id = p_id / OBJN;            // 0..319 == q*80 + b*20 + f
        int o  = p_id - id * OBJN;
        int q  = id / 80;
        int rem = id - q * 80;
        int b  = rem / FR;
        int f  = rem - b * FR;
        int bq = b * QQ + q;
        if (f == g_high[bq] || f == g_low[bq]) return;   // k_out_spec handles

        size_t outoff = ((size_t)id * OBJN + o) * DD;
        float4* op = (float4*)(out + outoff);                 // Rp
        float4* on = (float4*)(out + RP_ELEMS + outoff);      // Rn
        const float4* pr = (const float4*)(inp + (((size_t)(b * FR + f)) * OBJN + o) * DD);
        float invn = g_invn[(b * FR + f) * OBJN + o];

        #pragma unroll
        for (int i = 0; i < 4; i++) {
            float4 v = __ldg(pr + t + i * 256);
            v.x *= invn; v.y *= invn; v.z *= invn; v.w *= invn;
            __stcs(op + t + i * 256, v);
            __stcs(on + t + i * 256, v);
        }
    }
}

// ---------------- K4: hi/lo output frames (needs g_sim) ---------------------
__global__ void __launch_bounds__(256) k_out_spec(const float* __restrict__ inp,
                                                  const float* __restrict__ mem1,
                                                  const float* __restrict__ mem2,
                                                  float* __restrict__ out) {
    int s  = blockIdx.x;             // 0..31: [kind][bq]
    int o  = blockIdx.y;             // 0..19
    int bq = s & 15;
    int kind = s >> 4;               // 0: f=hi, 1: f=lo
    int b = bq >> 2, q = bq & 3;
    int hi = g_high[bq], lo = g_low[bq];
    int f  = kind ? lo : hi;
    int id = q * 80 + b * FR + f;
    int t  = threadIdx.x;

    size_t outoff = ((size_t)id * OBJN + o) * DD;
    float4* op = (float4*)(out + outoff);                 // Rp
    float4* on = (float4*)(out + RP_ELEMS + outoff);      // Rn
    const float4* pr = (const float4*)(inp + (((size_t)(b * FR + f)) * OBJN + o) * DD);
    float invn = g_invn[(b * FR + f) * OBJN + o];

    if (kind == 0) {
        // f == hi: Rn <- mem2[sim2 @ low]; Rp <- R
        int sm = g_sim[32 + 16 + bq];
        const float4* pm = (const float4*)(mem2 + (size_t)sm * (OBJN * DD) + o * DD);
        #pragma unroll
        for (int i = 0; i < 4; i++) {
            float4 v = __ldg(pr + t + i * 256);
            v.x *= invn; v.y *= invn; v.z *= invn; v.w *= invn;
            __stcs(op + t + i * 256, v);
            float4 w = __ldg(pm + t + i * 256);
            __stcs(on + t + i * 256, w);
        }
    } else {
        // f == lo: Rp <- mem1[sim1 @ low]; Rn <- R
        int sm = g_sim[16 + bq];
        const float4* pm = (const float4*)(mem1 + (size_t)sm * (OBJN * DD) + o * DD);
        #pragma unroll
        for (int i = 0; i < 4; i++) {
            float4 w = __ldg(pm + t + i * 256);
            __stcs(op + t + i * 256, w);
            float4 v = __ldg(pr + t + i * 256);
            v.x *= invn; v.y *= invn; v.z *= invn; v.w *= invn;
            __stcs(on + t + i * 256, v);
        }
    }
}

// ---------------- launch -----------------------------------------------------
extern "C" void kernel_launch(void* const* d_in, const int* in_sizes, int n_in,
                              void* d_out, int out_size) {
    const float* qr   = (const float*)d_in[0];   // [4,4,20]
    const float* inp  = (const float*)d_in[1];   // [4,20,20,4096]
    const float* mem1 = (const float*)d_in[2];   // [1000,81920]
    const float* mem2 = (const float*)d_in[3];   // [1000,81920]
    const int*   rnd  = (const int*)d_in[4];     // [4,4,1]
    float* out = (float*)d_out;

    k_norms<<<1600, 256>>>(qr, rnd, inp);
    k_pool<<<dim3(80, 4), 256>>>(inp);
    k_main<<<GRIDN, 256>>>(mem1, mem2, inp, out);
    k_out_spec<<<dim3(32, OBJN), 256>>>(inp, mem1, mem2, out);
}